// round 8
// baseline (speedup 1.0000x reference)
#include <cuda_runtime.h>
#include <cuda_fp16.h>

#define NV 196608
#define DEG 9

typedef unsigned long long ull;

__device__ __forceinline__ ull pk2(float a, float b) {
    ull r; asm("mov.b64 %0, {%1,%2};" : "=l"(r) : "f"(a), "f"(b)); return r;
}
__device__ __forceinline__ void upk2(ull v, float& a, float& b) {
    asm("mov.b64 {%0,%1}, %2;" : "=f"(a), "=f"(b) : "l"(v));
}
__device__ __forceinline__ ull fma2(ull a, ull b, ull c) {
    ull d; asm("fma.rn.f32x2 %0, %1, %2, %3;" : "=l"(d) : "l"(a), "l"(b), "l"(c)); return d;
}
union H4 { ull u; __half2 h[2]; };
__device__ __forceinline__ ull pack_h4(float x, float y, float z, float w) {
    H4 p;
    p.h[0] = __floats2half2_rn(x, y);
    p.h[1] = __floats2half2_rn(z, w);
    return p.u;
}

// ---------------- scratch ---------------------------------------------------
__device__ float  g_xT[(size_t)NV * 32];   // [V, b0 f0-15 | b1 f0-15]
__device__ float  g_t1[(size_t)NV * 32];   // L xT
__device__ float  g_h1[(size_t)NV * 64];   // layer1 pre-BN (fp32 stream copy)
__device__ __half g_h1h[(size_t)NV * 64];  // fp16 gather copy of h1
__device__ float  g_t2[(size_t)NV * 64];   // L relu(bn1(h1)) (fp32 stream copy)
__device__ __half g_t2h[(size_t)NV * 64];  // fp16 gather copy of t2
__device__ float  g_h2[(size_t)NV * 64];   // layer2 pre-BN
__device__ float  g_stats[128];            // [sum1, ss1, sum2, ss2] x32
__device__ float  g_sb[128];               // [scale1, bias1, scale2, bias2] x32

// ---------------- K0 --------------------------------------------------------
__global__ void k_zero_stats() {
    if (threadIdx.x < 128) g_stats[threadIdx.x] = 0.0f;
}

// ---------------- K1: transpose x [B,V,16] -> xT [V,32] ---------------------
__global__ void k_transpose(const float* __restrict__ x) {
    const int total = NV * 8;
    for (int idx = blockIdx.x * blockDim.x + threadIdx.x; idx < total;
         idx += gridDim.x * blockDim.x) {
        int v = idx >> 3;
        int j = idx & 7;
        int c0 = j * 4;
        int b = c0 >> 4;
        int f = c0 & 15;
        float4 val = *(const float4*)(x + (size_t)b * NV * 16 + (size_t)v * 16 + f);
        *(float4*)(g_xT + (size_t)v * 32 + c0) = val;
    }
}

// ---------------- K2: t1 = L xT (4 vertices/warp) ---------------------------
__global__ void k_spmv32(const int* __restrict__ cols,
                         const float* __restrict__ vals) {
    int lane = threadIdx.x & 31;
    int q = lane >> 3, r = lane & 7;
    int gw = (blockIdx.x * blockDim.x + threadIdx.x) >> 5;
    int nw = (gridDim.x * blockDim.x) >> 5;
    for (int v0 = gw * 4; v0 < NV; v0 += nw * 4) {
        int v = v0 + q;
        int eb = v * DEG;
        int   cj = cols[eb + r];
        float aj = vals[eb + r];
        int   c8 = cols[eb + 8];
        float a8 = vals[eb + 8];
        float4 acc = make_float4(0.f, 0.f, 0.f, 0.f);
        #pragma unroll
        for (int j = 0; j < 8; j++) {
            int   c = __shfl_sync(0xffffffffu, cj, (q << 3) + j);
            float a = __shfl_sync(0xffffffffu, aj, (q << 3) + j);
            float4 g = *(const float4*)(g_xT + (size_t)c * 32 + 4 * r);
            acc.x = fmaf(a, g.x, acc.x); acc.y = fmaf(a, g.y, acc.y);
            acc.z = fmaf(a, g.z, acc.z); acc.w = fmaf(a, g.w, acc.w);
        }
        {
            float4 g = *(const float4*)(g_xT + (size_t)c8 * 32 + 4 * r);
            acc.x = fmaf(a8, g.x, acc.x); acc.y = fmaf(a8, g.y, acc.y);
            acc.z = fmaf(a8, g.z, acc.z); acc.w = fmaf(a8, g.w, acc.w);
        }
        *(float4*)(g_t1 + (size_t)v * 32 + 4 * r) = acc;
    }
}

// ---------------- K3: fused layer1 (4 vertices/warp, FFMA2 matvec) ----------
__global__ void __launch_bounds__(128) k_fused1(const int* __restrict__ cols,
                                                const float* __restrict__ vals,
                                                const float* __restrict__ W1) {
    __shared__ float4 sIn[4][4][3][8];       // [warp][slot][arr][quad]
    __shared__ float bsum[32], bss[32];
    int tid = threadIdx.x, lane = tid & 31, w = tid >> 5;
    int q = lane >> 3, r = lane & 7;
    if (tid < 32) { bsum[tid] = 0.0f; bss[tid] = 0.0f; }
    ull wzp[8], wwp[8], wup[8];
    #pragma unroll
    for (int j = 0; j < 8; j++) {
        float a0 = W1[(2*j) * 32 + lane],   a1 = W1[(2*j+1) * 32 + lane];
        float b0 = W1[512 + (2*j)*32 + lane], b1 = W1[512 + (2*j+1)*32 + lane];
        float c0 = W1[1024 + (2*j)*32 + lane], c1 = W1[1024 + (2*j+1)*32 + lane];
        wzp[j] = pk2(a0 - c0, a1 - c1);
        wwp[j] = pk2(b0, b1);
        wup[j] = pk2(2.0f * c0, 2.0f * c1);
    }
    __syncthreads();

    int gw = blockIdx.x * 4 + w, nw = gridDim.x * 4;
    float ls = 0.0f, lss = 0.0f;

    for (int v0 = gw * 4; v0 < NV; v0 += nw * 4) {
        int v = v0 + q;
        int eb = v * DEG;
        int   cj = cols[eb + r];
        float aj = vals[eb + r];
        int   c8 = cols[eb + 8];
        float a8 = vals[eb + 8];
        float4 s4 = make_float4(0.f, 0.f, 0.f, 0.f);
        #pragma unroll
        for (int j = 0; j < 8; j++) {
            int   c = __shfl_sync(0xffffffffu, cj, (q << 3) + j);
            float a = __shfl_sync(0xffffffffu, aj, (q << 3) + j);
            float4 g = *(const float4*)(g_t1 + (size_t)c * 32 + 4 * r);
            s4.x = fmaf(a, g.x, s4.x); s4.y = fmaf(a, g.y, s4.y);
            s4.z = fmaf(a, g.z, s4.z); s4.w = fmaf(a, g.w, s4.w);
        }
        {
            float4 g = *(const float4*)(g_t1 + (size_t)c8 * 32 + 4 * r);
            s4.x = fmaf(a8, g.x, s4.x); s4.y = fmaf(a8, g.y, s4.y);
            s4.z = fmaf(a8, g.z, s4.z); s4.w = fmaf(a8, g.w, s4.w);
        }
        float4 x4 = *(const float4*)(g_xT + (size_t)v * 32 + 4 * r);
        float4 t4 = *(const float4*)(g_t1 + (size_t)v * 32 + 4 * r);
        sIn[w][q][0][r] = x4;
        sIn[w][q][1][r] = t4;
        sIn[w][q][2][r] = s4;
        __syncwarp();
        #pragma unroll
        for (int q2 = 0; q2 < 4; q2++) {
            const ulonglong2* A0 = (const ulonglong2*)sIn[w][q2][0];
            const ulonglong2* A1 = (const ulonglong2*)sIn[w][q2][1];
            const ulonglong2* A2 = (const ulonglong2*)sIn[w][q2][2];
            ull p0 = 0, p1 = 0;              // packed (even,odd) partials, b0/b1
            #pragma unroll
            for (int fp = 0; fp < 4; fp++) {
                ulonglong2 xa = A0[fp], xb = A0[4 + fp];
                p0 = fma2(xa.x, wzp[2*fp], p0); p0 = fma2(xa.y, wzp[2*fp+1], p0);
                p1 = fma2(xb.x, wzp[2*fp], p1); p1 = fma2(xb.y, wzp[2*fp+1], p1);
                ulonglong2 ta = A1[fp], tb = A1[4 + fp];
                p0 = fma2(ta.x, wwp[2*fp], p0); p0 = fma2(ta.y, wwp[2*fp+1], p0);
                p1 = fma2(tb.x, wwp[2*fp], p1); p1 = fma2(tb.y, wwp[2*fp+1], p1);
                ulonglong2 sa = A2[fp], sb = A2[4 + fp];
                p0 = fma2(sa.x, wup[2*fp], p0); p0 = fma2(sa.y, wup[2*fp+1], p0);
                p1 = fma2(sb.x, wup[2*fp], p1); p1 = fma2(sb.y, wup[2*fp+1], p1);
            }
            float e0, o0, e1, o1;
            upk2(p0, e0, o0); upk2(p1, e1, o1);
            float acc0 = e0 + o0, acc1 = e1 + o1;
            size_t row = (size_t)(v0 + q2) * 64;
            g_h1[row + lane] = acc0;
            g_h1[row + 32 + lane] = acc1;
            g_h1h[row + lane] = __float2half_rn(acc0);
            g_h1h[row + 32 + lane] = __float2half_rn(acc1);
            ls += acc0 + acc1;
            lss = fmaf(acc0, acc0, lss);
            lss = fmaf(acc1, acc1, lss);
        }
        __syncwarp();
    }
    atomicAdd(&bsum[lane], ls);
    atomicAdd(&bss[lane], lss);
    __syncthreads();
    if (tid < 32) {
        atomicAdd(&g_stats[tid], bsum[tid]);
        atomicAdd(&g_stats[32 + tid], bss[tid]);
    }
}

// ---------------- K4: finalize BN stats -> scale/bias -----------------------
__global__ void k_finalize(const float* __restrict__ gamma,
                           const float* __restrict__ beta, int which) {
    int c = threadIdx.x;
    if (c >= 32) return;
    float n = (float)(2 * NV);
    float sum = g_stats[which * 64 + c];
    float ss = g_stats[which * 64 + 32 + c];
    float mean = sum / n;
    float var = ss / n - mean * mean;
    float rstd = rsqrtf(var + 1e-5f);
    float sc = gamma[c] * rstd;
    g_sb[which * 64 + c] = sc;
    g_sb[which * 64 + 32 + c] = beta[c] - mean * sc;
}

// ---------------- K5: t2 = L relu(bn1(h1)) (fp16 gather, 2 v/warp) ----------
__global__ void k_spmv64_bn(const int* __restrict__ cols,
                            const float* __restrict__ vals) {
    int lane = threadIdx.x & 31;
    int q = lane >> 4, r = lane & 15;
    int gw = (blockIdx.x * blockDim.x + threadIdx.x) >> 5;
    int nw = (gridDim.x * blockDim.x) >> 5;
    int ch = (4 * r) & 31;
    float4 sc4 = *(const float4*)(g_sb + ch);
    float4 bi4 = *(const float4*)(g_sb + 32 + ch);
    for (int v0 = gw * 2; v0 < NV; v0 += nw * 2) {
        int v = v0 + q;
        int eb = v * DEG;
        int   cj = (r < 8) ? cols[eb + r] : 0;
        float aj = (r < 8) ? vals[eb + r] : 0.0f;
        int   c8 = cols[eb + 8];
        float a8 = vals[eb + 8];
        float4 acc = make_float4(0.f, 0.f, 0.f, 0.f);
        #pragma unroll
        for (int j = 0; j < 8; j++) {
            int   c = __shfl_sync(0xffffffffu, cj, (q << 4) + j);
            float a = __shfl_sync(0xffffffffu, aj, (q << 4) + j);
            H4 hraw; hraw.u = *(const ull*)(g_h1h + (size_t)c * 64 + 4 * r);
            float2 lo = __half22float2(hraw.h[0]);
            float2 hi = __half22float2(hraw.h[1]);
            acc.x = fmaf(a, fmaxf(fmaf(lo.x, sc4.x, bi4.x), 0.0f), acc.x);
            acc.y = fmaf(a, fmaxf(fmaf(lo.y, sc4.y, bi4.y), 0.0f), acc.y);
            acc.z = fmaf(a, fmaxf(fmaf(hi.x, sc4.z, bi4.z), 0.0f), acc.z);
            acc.w = fmaf(a, fmaxf(fmaf(hi.y, sc4.w, bi4.w), 0.0f), acc.w);
        }
        {
            H4 hraw; hraw.u = *(const ull*)(g_h1h + (size_t)c8 * 64 + 4 * r);
            float2 lo = __half22float2(hraw.h[0]);
            float2 hi = __half22float2(hraw.h[1]);
            acc.x = fmaf(a8, fmaxf(fmaf(lo.x, sc4.x, bi4.x), 0.0f), acc.x);
            acc.y = fmaf(a8, fmaxf(fmaf(lo.y, sc4.y, bi4.y), 0.0f), acc.y);
            acc.z = fmaf(a8, fmaxf(fmaf(hi.x, sc4.z, bi4.z), 0.0f), acc.z);
            acc.w = fmaf(a8, fmaxf(fmaf(hi.y, sc4.w, bi4.w), 0.0f), acc.w);
        }
        *(float4*)(g_t2 + (size_t)v * 64 + 4 * r) = acc;
        *(ull*)(g_t2h + (size_t)v * 64 + 4 * r) = pack_h4(acc.x, acc.y, acc.z, acc.w);
    }
}

// ---------------- K6: fused layer2 (fp16 gather, FFMA2 matvec) --------------
__global__ void __launch_bounds__(128) k_fused2(const int* __restrict__ cols,
                                                const float* __restrict__ vals,
                                                const float* __restrict__ W2) {
    __shared__ float4 sIn[4][2][3][16];      // [warp][slot][arr][quad]
    __shared__ float bsum[32], bss[32];
    int tid = threadIdx.x, lane = tid & 31, w = tid >> 5;
    int q = lane >> 4, r = lane & 15;
    if (tid < 32) { bsum[tid] = 0.0f; bss[tid] = 0.0f; }
    ull wap[16], wtp[16], wsp[16];
    #pragma unroll
    for (int j = 0; j < 16; j++) {
        float a0 = W2[(2*j)*32 + lane],        a1 = W2[(2*j+1)*32 + lane];
        float b0 = W2[1024 + (2*j)*32 + lane], b1 = W2[1024 + (2*j+1)*32 + lane];
        float c0 = W2[2048 + (2*j)*32 + lane], c1 = W2[2048 + (2*j+1)*32 + lane];
        wap[j] = pk2(a0 - c0, a1 - c1);
        wtp[j] = pk2(b0, b1);
        wsp[j] = pk2(2.0f * c0, 2.0f * c1);
    }
    int ch = (4 * r) & 31;
    float4 sc4 = *(const float4*)(g_sb + ch);
    float4 bi4 = *(const float4*)(g_sb + 32 + ch);
    __syncthreads();

    int gw = blockIdx.x * 4 + w, nw = gridDim.x * 4;
    float ls = 0.0f, lss = 0.0f;

    for (int v0 = gw * 2; v0 < NV; v0 += nw * 2) {
        int v = v0 + q;
        int eb = v * DEG;
        int   cj = (r < 8) ? cols[eb + r] : 0;
        float aj = (r < 8) ? vals[eb + r] : 0.0f;
        int   c8 = cols[eb + 8];
        float a8 = vals[eb + 8];
        float4 s4 = make_float4(0.f, 0.f, 0.f, 0.f);
        #pragma unroll
        for (int j = 0; j < 8; j++) {
            int   c = __shfl_sync(0xffffffffu, cj, (q << 4) + j);
            float a = __shfl_sync(0xffffffffu, aj, (q << 4) + j);
            H4 graw; graw.u = *(const ull*)(g_t2h + (size_t)c * 64 + 4 * r);
            float2 lo = __half22float2(graw.h[0]);
            float2 hi = __half22float2(graw.h[1]);
            s4.x = fmaf(a, lo.x, s4.x); s4.y = fmaf(a, lo.y, s4.y);
            s4.z = fmaf(a, hi.x, s4.z); s4.w = fmaf(a, hi.y, s4.w);
        }
        {
            H4 graw; graw.u = *(const ull*)(g_t2h + (size_t)c8 * 64 + 4 * r);
            float2 lo = __half22float2(graw.h[0]);
            float2 hi = __half22float2(graw.h[1]);
            s4.x = fmaf(a8, lo.x, s4.x); s4.y = fmaf(a8, lo.y, s4.y);
            s4.z = fmaf(a8, hi.x, s4.z); s4.w = fmaf(a8, hi.y, s4.w);
        }
        float4 hv = *(const float4*)(g_h1 + (size_t)v * 64 + 4 * r);
        float4 a14;
        a14.x = fmaxf(fmaf(hv.x, sc4.x, bi4.x), 0.0f);
        a14.y = fmaxf(fmaf(hv.y, sc4.y, bi4.y), 0.0f);
        a14.z = fmaxf(fmaf(hv.z, sc4.z, bi4.z), 0.0f);
        a14.w = fmaxf(fmaf(hv.w, sc4.w, bi4.w), 0.0f);
        float4 t4 = *(const float4*)(g_t2 + (size_t)v * 64 + 4 * r);
        sIn[w][q][0][r] = a14;
        sIn[w][q][1][r] = t4;
        sIn[w][q][2][r] = s4;
        __syncwarp();
        #pragma unroll
        for (int q2 = 0; q2 < 2; q2++) {
            const ulonglong2* A0 = (const ulonglong2*)sIn[w][q2][0];
            const ulonglong2* A1 = (const ulonglong2*)sIn[w][q2][1];
            const ulonglong2* A2 = (const ulonglong2*)sIn[w][q2][2];
            ull p0 = 0, p1 = 0;
            #pragma unroll
            for (int fp = 0; fp < 8; fp++) {
                ulonglong2 xa = A0[fp], xb = A0[8 + fp];
                p0 = fma2(xa.x, wap[2*fp], p0); p0 = fma2(xa.y, wap[2*fp+1], p0);
                p1 = fma2(xb.x, wap[2*fp], p1); p1 = fma2(xb.y, wap[2*fp+1], p1);
                ulonglong2 ta = A1[fp], tb = A1[8 + fp];
                p0 = fma2(ta.x, wtp[2*fp], p0); p0 = fma2(ta.y, wtp[2*fp+1], p0);
                p1 = fma2(tb.x, wtp[2*fp], p1); p1 = fma2(tb.y, wtp[2*fp+1], p1);
                ulonglong2 sa = A2[fp], sb = A2[8 + fp];
                p0 = fma2(sa.x, wsp[2*fp], p0); p0 = fma2(sa.y, wsp[2*fp+1], p0);
                p1 = fma2(sb.x, wsp[2*fp], p1); p1 = fma2(sb.y, wsp[2*fp+1], p1);
            }
            float e0, o0, e1, o1;
            upk2(p0, e0, o0); upk2(p1, e1, o1);
            float acc0 = e0 + o0, acc1 = e1 + o1;
            g_h2[(size_t)(v0 + q2) * 64 + lane] = acc0;
            g_h2[(size_t)(v0 + q2) * 64 + 32 + lane] = acc1;
            ls += acc0 + acc1;
            lss = fmaf(acc0, acc0, lss);
            lss = fmaf(acc1, acc1, lss);
        }
        __syncwarp();
    }
    atomicAdd(&bsum[lane], ls);
    atomicAdd(&bss[lane], lss);
    __syncthreads();
    if (tid < 32) {
        atomicAdd(&g_stats[64 + tid], bsum[tid]);
        atomicAdd(&g_stats[96 + tid], bss[tid]);
    }
}

// ---------------- K7: out = relu(bn2(h2)), layout [B,V,32] ------------------
__global__ void k_output(float* __restrict__ out) {
    const int total = NV * 16;
    for (int idx = blockIdx.x * blockDim.x + threadIdx.x; idx < total;
         idx += gridDim.x * blockDim.x) {
        int v = idx >> 4;
        int j = idx & 15;
        int col = j * 4;
        int ch = col & 31;
        int b = col >> 5;
        float4 hv = *(const float4*)(g_h2 + (size_t)v * 64 + col);
        float4 r;
        r.x = fmaxf(fmaf(hv.x, g_sb[64 + ch],     g_sb[96 + ch]),     0.0f);
        r.y = fmaxf(fmaf(hv.y, g_sb[64 + ch + 1], g_sb[96 + ch + 1]), 0.0f);
        r.z = fmaxf(fmaf(hv.z, g_sb[64 + ch + 2], g_sb[96 + ch + 2]), 0.0f);
        r.w = fmaxf(fmaf(hv.w, g_sb[64 + ch + 3], g_sb[96 + ch + 3]), 0.0f);
        *(float4*)(out + (size_t)b * NV * 32 + (size_t)v * 32 + ch) = r;
    }
}

// ---------------- launch ----------------------------------------------------
extern "C" void kernel_launch(void* const* d_in, const int* in_sizes, int n_in,
                              void* d_out, int out_size) {
    const float* x    = (const float*)d_in[0];
    const int*   cols = (const int*)d_in[2];
    const float* vals = (const float*)d_in[3];
    const float* W1   = (const float*)d_in[4];
    const float* g1   = (const float*)d_in[5];
    const float* b1   = (const float*)d_in[6];
    const float* W2   = (const float*)d_in[7];
    const float* g2   = (const float*)d_in[8];
    const float* b2   = (const float*)d_in[9];
    float*       out  = (float*)d_out;

    const int GRID_G = 1184;      // gather kernels, 256 thr
    const int GRID_F = 2368;      // fused kernels, 128 thr

    k_zero_stats<<<1, 128>>>();
    k_transpose<<<2048, 256>>>(x);
    k_spmv32<<<GRID_G, 256>>>(cols, vals);
    k_fused1<<<GRID_F, 128>>>(cols, vals, W1);
    k_finalize<<<1, 32>>>(g1, b1, 0);
    k_spmv64_bn<<<GRID_G, 256>>>(cols, vals);
    k_fused2<<<GRID_F, 128>>>(cols, vals, W2);
    k_finalize<<<1, 32>>>(g2, b2, 1);
    k_output<<<2048, 256>>>(out);
}

// round 10
// speedup vs baseline: 1.4162x; 1.4162x over previous
#include <cuda_runtime.h>

#define NV 196608
#define DEG 9

// ---------------- scratch ---------------------------------------------------
__device__ float g_t1[(size_t)NV * 32];   // L x   [V, b0 f0-15 | b1 f0-15]
__device__ float g_h1[(size_t)NV * 64];   // layer1 pre-BN  [V, b0 o0-31 | b1 o0-31]
__device__ float g_t2[(size_t)NV * 64];   // L relu(bn1(h1))
__device__ float g_h2[(size_t)NV * 64];   // layer2 pre-BN
__device__ float g_stats[128];            // [sum1, ss1, sum2, ss2] x32
__device__ float g_sb[128];               // [scale1, bias1, scale2, bias2] x32

// ---------------- K0 --------------------------------------------------------
__global__ void k_zero_stats() {
    if (threadIdx.x < 128) g_stats[threadIdx.x] = 0.0f;
}

// ---------------- K2: t1 = L x (4 vertices/warp, direct-from-x gather) ------
// lane r in [0,8): covers t1 cols 4r..4r+3 == x[b=r>>2][.][f=4*(r&3)..+3]
__global__ void k_spmv32(const int* __restrict__ cols,
                         const float* __restrict__ vals,
                         const float* __restrict__ x) {
    int lane = threadIdx.x & 31;
    int q = lane >> 3, r = lane & 7;
    size_t xoff = (size_t)(r >> 2) * NV * 16 + 4 * (r & 3);
    int gw = (blockIdx.x * blockDim.x + threadIdx.x) >> 5;
    int nw = (gridDim.x * blockDim.x) >> 5;
    int step = nw * 4;
    int v0 = gw * 4;
    int cjN = 0, c8N = 0; float ajN = 0.0f, a8N = 0.0f;
    if (v0 < NV) {
        int eb = (v0 + q) * DEG;
        cjN = cols[eb + r]; ajN = vals[eb + r];
        c8N = cols[eb + 8]; a8N = vals[eb + 8];
    }
    for (; v0 < NV; v0 += step) {
        int cj = cjN; float aj = ajN; int c8 = c8N; float a8 = a8N;
        int vn = v0 + step;
        if (vn < NV) {
            int eb = (vn + q) * DEG;
            cjN = cols[eb + r]; ajN = vals[eb + r];
            c8N = cols[eb + 8]; a8N = vals[eb + 8];
        }
        float4 acc = make_float4(0.f, 0.f, 0.f, 0.f);
        #pragma unroll
        for (int j = 0; j < 8; j++) {
            int   c = __shfl_sync(0xffffffffu, cj, (q << 3) + j);
            float a = __shfl_sync(0xffffffffu, aj, (q << 3) + j);
            float4 g = *(const float4*)(x + xoff + (size_t)c * 16);
            acc.x = fmaf(a, g.x, acc.x); acc.y = fmaf(a, g.y, acc.y);
            acc.z = fmaf(a, g.z, acc.z); acc.w = fmaf(a, g.w, acc.w);
        }
        {
            float4 g = *(const float4*)(x + xoff + (size_t)c8 * 16);
            acc.x = fmaf(a8, g.x, acc.x); acc.y = fmaf(a8, g.y, acc.y);
            acc.z = fmaf(a8, g.z, acc.z); acc.w = fmaf(a8, g.w, acc.w);
        }
        *(float4*)(g_t1 + (size_t)(v0 + q) * 32 + 4 * r) = acc;
    }
}

// ---------------- K3: fused layer1 (4 vertices/warp, edge prefetch) ---------
// s = L t1; h1 = x*(W0-W2) + t1*W1 + s*(2W2); BN stats.
__global__ void __launch_bounds__(128) k_fused1(const int* __restrict__ cols,
                                                const float* __restrict__ vals,
                                                const float* __restrict__ W1,
                                                const float* __restrict__ x) {
    __shared__ float4 sIn[4][4][3][8];       // [warp][slot][arr][quad]
    __shared__ float bsum[32], bss[32];
    int tid = threadIdx.x, lane = tid & 31, w = tid >> 5;
    int q = lane >> 3, r = lane & 7;
    size_t xoff = (size_t)(r >> 2) * NV * 16 + 4 * (r & 3);
    if (tid < 32) { bsum[tid] = 0.0f; bss[tid] = 0.0f; }
    float wz[16], ww[16], wu[16];
    #pragma unroll
    for (int f = 0; f < 16; f++) {
        float a = W1[f * 32 + lane];
        float b = W1[512 + f * 32 + lane];
        float c = W1[1024 + f * 32 + lane];
        wz[f] = a - c; ww[f] = b; wu[f] = 2.0f * c;
    }
    __syncthreads();

    int gw = blockIdx.x * 4 + w, nw = gridDim.x * 4;
    int step = nw * 4;
    float ls = 0.0f, lss = 0.0f;
    int v0 = gw * 4;
    int cjN = 0, c8N = 0; float ajN = 0.0f, a8N = 0.0f;
    if (v0 < NV) {
        int eb = (v0 + q) * DEG;
        cjN = cols[eb + r]; ajN = vals[eb + r];
        c8N = cols[eb + 8]; a8N = vals[eb + 8];
    }

    for (; v0 < NV; v0 += step) {
        int v = v0 + q;
        int cj = cjN; float aj = ajN; int c8 = c8N; float a8 = a8N;
        int vn = v0 + step;
        if (vn < NV) {
            int eb = (vn + q) * DEG;
            cjN = cols[eb + r]; ajN = vals[eb + r];
            c8N = cols[eb + 8]; a8N = vals[eb + 8];
        }
        float4 s4 = make_float4(0.f, 0.f, 0.f, 0.f);
        #pragma unroll
        for (int j = 0; j < 8; j++) {
            int   c = __shfl_sync(0xffffffffu, cj, (q << 3) + j);
            float a = __shfl_sync(0xffffffffu, aj, (q << 3) + j);
            float4 g = *(const float4*)(g_t1 + (size_t)c * 32 + 4 * r);
            s4.x = fmaf(a, g.x, s4.x); s4.y = fmaf(a, g.y, s4.y);
            s4.z = fmaf(a, g.z, s4.z); s4.w = fmaf(a, g.w, s4.w);
        }
        {
            float4 g = *(const float4*)(g_t1 + (size_t)c8 * 32 + 4 * r);
            s4.x = fmaf(a8, g.x, s4.x); s4.y = fmaf(a8, g.y, s4.y);
            s4.z = fmaf(a8, g.z, s4.z); s4.w = fmaf(a8, g.w, s4.w);
        }
        float4 x4 = *(const float4*)(x + xoff + (size_t)v * 16);
        float4 t4 = *(const float4*)(g_t1 + (size_t)v * 32 + 4 * r);
        sIn[w][q][0][r] = x4;
        sIn[w][q][1][r] = t4;
        sIn[w][q][2][r] = s4;
        __syncwarp();
        #pragma unroll
        for (int q2 = 0; q2 < 4; q2++) {
            float acc0 = 0.0f, acc1 = 0.0f;
            #pragma unroll
            for (int fp = 0; fp < 4; fp++) {     // f quad, b0 at fp, b1 at fp+4
                float4 pa = sIn[w][q2][0][fp];
                float4 pb = sIn[w][q2][0][fp + 4];
                acc0 = fmaf(pa.x, wz[4*fp], acc0);   acc1 = fmaf(pb.x, wz[4*fp], acc1);
                acc0 = fmaf(pa.y, wz[4*fp+1], acc0); acc1 = fmaf(pb.y, wz[4*fp+1], acc1);
                acc0 = fmaf(pa.z, wz[4*fp+2], acc0); acc1 = fmaf(pb.z, wz[4*fp+2], acc1);
                acc0 = fmaf(pa.w, wz[4*fp+3], acc0); acc1 = fmaf(pb.w, wz[4*fp+3], acc1);
                float4 ta = sIn[w][q2][1][fp];
                float4 tb = sIn[w][q2][1][fp + 4];
                acc0 = fmaf(ta.x, ww[4*fp], acc0);   acc1 = fmaf(tb.x, ww[4*fp], acc1);
                acc0 = fmaf(ta.y, ww[4*fp+1], acc0); acc1 = fmaf(tb.y, ww[4*fp+1], acc1);
                acc0 = fmaf(ta.z, ww[4*fp+2], acc0); acc1 = fmaf(tb.z, ww[4*fp+2], acc1);
                acc0 = fmaf(ta.w, ww[4*fp+3], acc0); acc1 = fmaf(tb.w, ww[4*fp+3], acc1);
                float4 sa = sIn[w][q2][2][fp];
                float4 sb = sIn[w][q2][2][fp + 4];
                acc0 = fmaf(sa.x, wu[4*fp], acc0);   acc1 = fmaf(sb.x, wu[4*fp], acc1);
                acc0 = fmaf(sa.y, wu[4*fp+1], acc0); acc1 = fmaf(sb.y, wu[4*fp+1], acc1);
                acc0 = fmaf(sa.z, wu[4*fp+2], acc0); acc1 = fmaf(sb.z, wu[4*fp+2], acc1);
                acc0 = fmaf(sa.w, wu[4*fp+3], acc0); acc1 = fmaf(sb.w, wu[4*fp+3], acc1);
            }
            g_h1[(size_t)(v0 + q2) * 64 + lane] = acc0;
            g_h1[(size_t)(v0 + q2) * 64 + 32 + lane] = acc1;
            ls += acc0 + acc1;
            lss = fmaf(acc0, acc0, lss);
            lss = fmaf(acc1, acc1, lss);
        }
        __syncwarp();
    }
    atomicAdd(&bsum[lane], ls);
    atomicAdd(&bss[lane], lss);
    __syncthreads();
    if (tid < 32) {
        atomicAdd(&g_stats[tid], bsum[tid]);
        atomicAdd(&g_stats[32 + tid], bss[tid]);
    }
}

// ---------------- K4: finalize BN stats -> scale/bias -----------------------
__global__ void k_finalize(const float* __restrict__ gamma,
                           const float* __restrict__ beta, int which) {
    int c = threadIdx.x;
    if (c >= 32) return;
    float n = (float)(2 * NV);
    float sum = g_stats[which * 64 + c];
    float ss = g_stats[which * 64 + 32 + c];
    float mean = sum / n;
    float var = ss / n - mean * mean;
    float rstd = rsqrtf(var + 1e-5f);
    float sc = gamma[c] * rstd;
    g_sb[which * 64 + c] = sc;
    g_sb[which * 64 + 32 + c] = beta[c] - mean * sc;
}

// ---------------- K5: t2 = L relu(bn1(h1)) (2 vertices/warp, prefetch) ------
__global__ void k_spmv64_bn(const int* __restrict__ cols,
                            const float* __restrict__ vals) {
    int lane = threadIdx.x & 31;
    int q = lane >> 4, r = lane & 15;
    int gw = (blockIdx.x * blockDim.x + threadIdx.x) >> 5;
    int nw = (gridDim.x * blockDim.x) >> 5;
    int step = nw * 2;
    int ch = (4 * r) & 31;
    float4 sc4 = *(const float4*)(g_sb + ch);
    float4 bi4 = *(const float4*)(g_sb + 32 + ch);
    int v0 = gw * 2;
    int cjN = 0, c8N = 0; float ajN = 0.0f, a8N = 0.0f;
    if (v0 < NV) {
        int eb = (v0 + q) * DEG;
        cjN = (r < 8) ? cols[eb + r] : 0;
        ajN = (r < 8) ? vals[eb + r] : 0.0f;
        c8N = cols[eb + 8]; a8N = vals[eb + 8];
    }
    for (; v0 < NV; v0 += step) {
        int v = v0 + q;
        int cj = cjN; float aj = ajN; int c8 = c8N; float a8 = a8N;
        int vn = v0 + step;
        if (vn < NV) {
            int eb = (vn + q) * DEG;
            cjN = (r < 8) ? cols[eb + r] : 0;
            ajN = (r < 8) ? vals[eb + r] : 0.0f;
            c8N = cols[eb + 8]; a8N = vals[eb + 8];
        }
        float4 acc = make_float4(0.f, 0.f, 0.f, 0.f);
        #pragma unroll
        for (int j = 0; j < 8; j++) {
            int   c = __shfl_sync(0xffffffffu, cj, (q << 4) + j);
            float a = __shfl_sync(0xffffffffu, aj, (q << 4) + j);
            float4 g = *(const float4*)(g_h1 + (size_t)c * 64 + 4 * r);
            acc.x = fmaf(a, fmaxf(fmaf(g.x, sc4.x, bi4.x), 0.0f), acc.x);
            acc.y = fmaf(a, fmaxf(fmaf(g.y, sc4.y, bi4.y), 0.0f), acc.y);
            acc.z = fmaf(a, fmaxf(fmaf(g.z, sc4.z, bi4.z), 0.0f), acc.z);
            acc.w = fmaf(a, fmaxf(fmaf(g.w, sc4.w, bi4.w), 0.0f), acc.w);
        }
        {
            float4 g = *(const float4*)(g_h1 + (size_t)c8 * 64 + 4 * r);
            acc.x = fmaf(a8, fmaxf(fmaf(g.x, sc4.x, bi4.x), 0.0f), acc.x);
            acc.y = fmaf(a8, fmaxf(fmaf(g.y, sc4.y, bi4.y), 0.0f), acc.y);
            acc.z = fmaf(a8, fmaxf(fmaf(g.z, sc4.z, bi4.z), 0.0f), acc.z);
            acc.w = fmaf(a8, fmaxf(fmaf(g.w, sc4.w, bi4.w), 0.0f), acc.w);
        }
        *(float4*)(g_t2 + (size_t)v * 64 + 4 * r) = acc;
    }
}

// ---------------- K6: fused layer2 (2 vertices/warp, prefetch) --------------
// s = L t2; h2 = a1*(W0-W2) + t2*W1 + s*(2W2), a1 = relu(bn1(h1)); BN stats.
__global__ void __launch_bounds__(128) k_fused2(const int* __restrict__ cols,
                                                const float* __restrict__ vals,
                                                const float* __restrict__ W2) {
    __shared__ float4 sIn[4][2][3][16];      // [warp][slot][arr][quad]
    __shared__ float bsum[32], bss[32];
    int tid = threadIdx.x, lane = tid & 31, w = tid >> 5;
    int q = lane >> 4, r = lane & 15;
    if (tid < 32) { bsum[tid] = 0.0f; bss[tid] = 0.0f; }
    float wa[32], wt[32], ws[32];
    #pragma unroll
    for (int f = 0; f < 32; f++) {
        float a = W2[f * 32 + lane];
        float b = W2[1024 + f * 32 + lane];
        float c = W2[2048 + f * 32 + lane];
        wa[f] = a - c; wt[f] = b; ws[f] = 2.0f * c;
    }
    int ch = (4 * r) & 31;
    float4 sc4 = *(const float4*)(g_sb + ch);
    float4 bi4 = *(const float4*)(g_sb + 32 + ch);
    __syncthreads();

    int gw = blockIdx.x * 4 + w, nw = gridDim.x * 4;
    int step = nw * 2;
    float ls = 0.0f, lss = 0.0f;
    int v0 = gw * 2;
    int cjN = 0, c8N = 0; float ajN = 0.0f, a8N = 0.0f;
    if (v0 < NV) {
        int eb = (v0 + q) * DEG;
        cjN = (r < 8) ? cols[eb + r] : 0;
        ajN = (r < 8) ? vals[eb + r] : 0.0f;
        c8N = cols[eb + 8]; a8N = vals[eb + 8];
    }

    for (; v0 < NV; v0 += step) {
        int v = v0 + q;
        int cj = cjN; float aj = ajN; int c8 = c8N; float a8 = a8N;
        int vn = v0 + step;
        if (vn < NV) {
            int eb = (vn + q) * DEG;
            cjN = (r < 8) ? cols[eb + r] : 0;
            ajN = (r < 8) ? vals[eb + r] : 0.0f;
            c8N = cols[eb + 8]; a8N = vals[eb + 8];
        }
        float4 s4 = make_float4(0.f, 0.f, 0.f, 0.f);
        #pragma unroll
        for (int j = 0; j < 8; j++) {
            int   c = __shfl_sync(0xffffffffu, cj, (q << 4) + j);
            float a = __shfl_sync(0xffffffffu, aj, (q << 4) + j);
            float4 g = *(const float4*)(g_t2 + (size_t)c * 64 + 4 * r);
            s4.x = fmaf(a, g.x, s4.x); s4.y = fmaf(a, g.y, s4.y);
            s4.z = fmaf(a, g.z, s4.z); s4.w = fmaf(a, g.w, s4.w);
        }
        {
            float4 g = *(const float4*)(g_t2 + (size_t)c8 * 64 + 4 * r);
            s4.x = fmaf(a8, g.x, s4.x); s4.y = fmaf(a8, g.y, s4.y);
            s4.z = fmaf(a8, g.z, s4.z); s4.w = fmaf(a8, g.w, s4.w);
        }
        float4 hv = *(const float4*)(g_h1 + (size_t)v * 64 + 4 * r);
        float4 a14;
        a14.x = fmaxf(fmaf(hv.x, sc4.x, bi4.x), 0.0f);
        a14.y = fmaxf(fmaf(hv.y, sc4.y, bi4.y), 0.0f);
        a14.z = fmaxf(fmaf(hv.z, sc4.z, bi4.z), 0.0f);
        a14.w = fmaxf(fmaf(hv.w, sc4.w, bi4.w), 0.0f);
        float4 t4 = *(const float4*)(g_t2 + (size_t)v * 64 + 4 * r);
        sIn[w][q][0][r] = a14;
        sIn[w][q][1][r] = t4;
        sIn[w][q][2][r] = s4;
        __syncwarp();
        #pragma unroll
        for (int q2 = 0; q2 < 2; q2++) {
            float acc0 = 0.0f, acc1 = 0.0f;
            #pragma unroll
            for (int fp = 0; fp < 8; fp++) {     // f quad, b0 at fp, b1 at fp+8
                float4 pa = sIn[w][q2][0][fp];
                float4 pb = sIn[w][q2][0][fp + 8];
                acc0 = fmaf(pa.x, wa[4*fp], acc0);   acc1 = fmaf(pb.x, wa[4*fp], acc1);
                acc0 = fmaf(pa.y, wa[4*fp+1], acc0); acc1 = fmaf(pb.y, wa[4*fp+1], acc1);
                acc0 = fmaf(pa.z, wa[4*fp+2], acc0); acc1 = fmaf(pb.z, wa[4*fp+2], acc1);
                acc0 = fmaf(pa.w, wa[4*fp+3], acc0); acc1 = fmaf(pb.w, wa[4*fp+3], acc1);
                float4 ta = sIn[w][q2][1][fp];
                float4 tb = sIn[w][q2][1][fp + 8];
                acc0 = fmaf(ta.x, wt[4*fp], acc0);   acc1 = fmaf(tb.x, wt[4*fp], acc1);
                acc0 = fmaf(ta.y, wt[4*fp+1], acc0); acc1 = fmaf(tb.y, wt[4*fp+1], acc1);
                acc0 = fmaf(ta.z, wt[4*fp+2], acc0); acc1 = fmaf(tb.z, wt[4*fp+2], acc1);
                acc0 = fmaf(ta.w, wt[4*fp+3], acc0); acc1 = fmaf(tb.w, wt[4*fp+3], acc1);
                float4 sa = sIn[w][q2][2][fp];
                float4 sb = sIn[w][q2][2][fp + 8];
                acc0 = fmaf(sa.x, ws[4*fp], acc0);   acc1 = fmaf(sb.x, ws[4*fp], acc1);
                acc0 = fmaf(sa.y, ws[4*fp+1], acc0); acc1 = fmaf(sb.y, ws[4*fp+1], acc1);
                acc0 = fmaf(sa.z, ws[4*fp+2], acc0); acc1 = fmaf(sb.z, ws[4*fp+2], acc1);
                acc0 = fmaf(sa.w, ws[4*fp+3], acc0); acc1 = fmaf(sb.w, ws[4*fp+3], acc1);
            }
            g_h2[(size_t)(v0 + q2) * 64 + lane] = acc0;
            g_h2[(size_t)(v0 + q2) * 64 + 32 + lane] = acc1;
            ls += acc0 + acc1;
            lss = fmaf(acc0, acc0, lss);
            lss = fmaf(acc1, acc1, lss);
        }
        __syncwarp();
    }
    atomicAdd(&bsum[lane], ls);
    atomicAdd(&bss[lane], lss);
    __syncthreads();
    if (tid < 32) {
        atomicAdd(&g_stats[64 + tid], bsum[tid]);
        atomicAdd(&g_stats[96 + tid], bss[tid]);
    }
}

// ---------------- K7: out = relu(bn2(h2)), layout [B,V,32] ------------------
__global__ void k_output(float* __restrict__ out) {
    const int total = NV * 16;
    for (int idx = blockIdx.x * blockDim.x + threadIdx.x; idx < total;
         idx += gridDim.x * blockDim.x) {
        int v = idx >> 4;
        int j = idx & 15;
        int col = j * 4;
        int ch = col & 31;
        int b = col >> 5;
        float4 hv = *(const float4*)(g_h2 + (size_t)v * 64 + col);
        float4 r;
        r.x = fmaxf(fmaf(hv.x, g_sb[64 + ch],     g_sb[96 + ch]),     0.0f);
        r.y = fmaxf(fmaf(hv.y, g_sb[64 + ch + 1], g_sb[96 + ch + 1]), 0.0f);
        r.z = fmaxf(fmaf(hv.z, g_sb[64 + ch + 2], g_sb[96 + ch + 2]), 0.0f);
        r.w = fmaxf(fmaf(hv.w, g_sb[64 + ch + 3], g_sb[96 + ch + 3]), 0.0f);
        *(float4*)(out + (size_t)b * NV * 32 + (size_t)v * 32 + ch) = r;
    }
}

// ---------------- launch ----------------------------------------------------
extern "C" void kernel_launch(void* const* d_in, const int* in_sizes, int n_in,
                              void* d_out, int out_size) {
    const float* x    = (const float*)d_in[0];
    const int*   cols = (const int*)d_in[2];
    const float* vals = (const float*)d_in[3];
    const float* W1   = (const float*)d_in[4];
    const float* g1   = (const float*)d_in[5];
    const float* b1   = (const float*)d_in[6];
    const float* W2   = (const float*)d_in[7];
    const float* g2   = (const float*)d_in[8];
    const float* b2   = (const float*)d_in[9];
    float*       out  = (float*)d_out;

    const int GRID_G = 1184;      // gather kernels, 256 thr
    const int GRID_F = 2368;      // fused kernels, 128 thr

    k_zero_stats<<<1, 128>>>();
    k_spmv32<<<GRID_G, 256>>>(cols, vals, x);
    k_fused1<<<GRID_F, 128>>>(cols, vals, W1, x);
    k_finalize<<<1, 32>>>(g1, b1, 0);
    k_spmv64_bn<<<GRID_G, 256>>>(cols, vals);
    k_fused2<<<GRID_F, 128>>>(cols, vals, W2);
    k_finalize<<<1, 32>>>(g2, b2, 1);
    k_output<<<2048, 256>>>(out);
}

// round 12
// speedup vs baseline: 1.4953x; 1.0558x over previous
#include <cuda_runtime.h>
#include <cuda_fp16.h>

#define NV 196608
#define DEG 9

typedef unsigned long long ull;
union H4 { ull u; __half2 h[2]; };

__device__ __forceinline__ ull pack_h4(float x, float y, float z, float w) {
    H4 p;
    p.h[0] = __floats2half2_rn(x, y);
    p.h[1] = __floats2half2_rn(z, w);
    return p.u;
}

// ---------------- scratch ---------------------------------------------------
__device__ float  g_t1[(size_t)NV * 32];   // L x   [V, b0 f0-15 | b1 f0-15]
__device__ __half g_h1h[(size_t)NV * 64];  // layer1 pre-BN (fp16 only)
__device__ __half g_t2h[(size_t)NV * 64];  // L relu(bn1(h1)) (fp16 only)
__device__ float  g_h2[(size_t)NV * 64];   // layer2 pre-BN (fp32)
__device__ float  g_stats[128];            // [sum1, ss1, sum2, ss2] x32

// ---------------- K1: t1 = L x (4 v/warp, direct-from-x, prefetch) ----------
// lane r in [0,8): t1 cols 4r..4r+3 == x[b=r>>2][.][f=4*(r&3)..+3]
__global__ void k_spmv32(const int* __restrict__ cols,
                         const float* __restrict__ vals,
                         const float* __restrict__ x) {
    if (blockIdx.x == 0 && threadIdx.x < 128) g_stats[threadIdx.x] = 0.0f;
    int lane = threadIdx.x & 31;
    int q = lane >> 3, r = lane & 7;
    size_t xoff = (size_t)(r >> 2) * NV * 16 + 4 * (r & 3);
    int gw = (blockIdx.x * blockDim.x + threadIdx.x) >> 5;
    int nw = (gridDim.x * blockDim.x) >> 5;
    int step = nw * 4;
    int v0 = gw * 4;
    int cjN = 0, c8N = 0; float ajN = 0.0f, a8N = 0.0f;
    if (v0 < NV) {
        int eb = (v0 + q) * DEG;
        cjN = cols[eb + r]; ajN = vals[eb + r];
        c8N = cols[eb + 8]; a8N = vals[eb + 8];
    }
    for (; v0 < NV; v0 += step) {
        int cj = cjN; float aj = ajN; int c8 = c8N; float a8 = a8N;
        int vn = v0 + step;
        if (vn < NV) {
            int eb = (vn + q) * DEG;
            cjN = cols[eb + r]; ajN = vals[eb + r];
            c8N = cols[eb + 8]; a8N = vals[eb + 8];
        }
        float4 acc = make_float4(0.f, 0.f, 0.f, 0.f);
        #pragma unroll
        for (int j = 0; j < 8; j++) {
            int   c = __shfl_sync(0xffffffffu, cj, (q << 3) + j);
            float a = __shfl_sync(0xffffffffu, aj, (q << 3) + j);
            float4 g = *(const float4*)(x + xoff + (size_t)c * 16);
            acc.x = fmaf(a, g.x, acc.x); acc.y = fmaf(a, g.y, acc.y);
            acc.z = fmaf(a, g.z, acc.z); acc.w = fmaf(a, g.w, acc.w);
        }
        {
            float4 g = *(const float4*)(x + xoff + (size_t)c8 * 16);
            acc.x = fmaf(a8, g.x, acc.x); acc.y = fmaf(a8, g.y, acc.y);
            acc.z = fmaf(a8, g.z, acc.z); acc.w = fmaf(a8, g.w, acc.w);
        }
        *(float4*)(g_t1 + (size_t)(v0 + q) * 32 + 4 * r) = acc;
    }
}

// ---------------- K2: fused layer1 (4 v/warp, prefetch, fp16 h1 store) ------
__global__ void __launch_bounds__(128) k_fused1(const int* __restrict__ cols,
                                                const float* __restrict__ vals,
                                                const float* __restrict__ W1,
                                                const float* __restrict__ x) {
    __shared__ float4 sIn[4][4][3][8];       // [warp][slot][arr][quad]
    __shared__ float bsum[32], bss[32];
    int tid = threadIdx.x, lane = tid & 31, w = tid >> 5;
    int q = lane >> 3, r = lane & 7;
    size_t xoff = (size_t)(r >> 2) * NV * 16 + 4 * (r & 3);
    if (tid < 32) { bsum[tid] = 0.0f; bss[tid] = 0.0f; }
    float wz[16], ww[16], wu[16];
    #pragma unroll
    for (int f = 0; f < 16; f++) {
        float a = W1[f * 32 + lane];
        float b = W1[512 + f * 32 + lane];
        float c = W1[1024 + f * 32 + lane];
        wz[f] = a - c; ww[f] = b; wu[f] = 2.0f * c;
    }
    __syncthreads();

    int gw = blockIdx.x * 4 + w, nw = gridDim.x * 4;
    int step = nw * 4;
    float ls = 0.0f, lss = 0.0f;
    int v0 = gw * 4;
    int cjN = 0, c8N = 0; float ajN = 0.0f, a8N = 0.0f;
    if (v0 < NV) {
        int eb = (v0 + q) * DEG;
        cjN = cols[eb + r]; ajN = vals[eb + r];
        c8N = cols[eb + 8]; a8N = vals[eb + 8];
    }

    for (; v0 < NV; v0 += step) {
        int v = v0 + q;
        int cj = cjN; float aj = ajN; int c8 = c8N; float a8 = a8N;
        int vn = v0 + step;
        if (vn < NV) {
            int eb = (vn + q) * DEG;
            cjN = cols[eb + r]; ajN = vals[eb + r];
            c8N = cols[eb + 8]; a8N = vals[eb + 8];
        }
        float4 s4 = make_float4(0.f, 0.f, 0.f, 0.f);
        #pragma unroll
        for (int j = 0; j < 8; j++) {
            int   c = __shfl_sync(0xffffffffu, cj, (q << 3) + j);
            float a = __shfl_sync(0xffffffffu, aj, (q << 3) + j);
            float4 g = *(const float4*)(g_t1 + (size_t)c * 32 + 4 * r);
            s4.x = fmaf(a, g.x, s4.x); s4.y = fmaf(a, g.y, s4.y);
            s4.z = fmaf(a, g.z, s4.z); s4.w = fmaf(a, g.w, s4.w);
        }
        {
            float4 g = *(const float4*)(g_t1 + (size_t)c8 * 32 + 4 * r);
            s4.x = fmaf(a8, g.x, s4.x); s4.y = fmaf(a8, g.y, s4.y);
            s4.z = fmaf(a8, g.z, s4.z); s4.w = fmaf(a8, g.w, s4.w);
        }
        float4 x4 = *(const float4*)(x + xoff + (size_t)v * 16);
        float4 t4 = *(const float4*)(g_t1 + (size_t)v * 32 + 4 * r);
        sIn[w][q][0][r] = x4;
        sIn[w][q][1][r] = t4;
        sIn[w][q][2][r] = s4;
        __syncwarp();
        #pragma unroll
        for (int q2 = 0; q2 < 4; q2++) {
            float acc0 = 0.0f, acc1 = 0.0f;
            #pragma unroll
            for (int fp = 0; fp < 4; fp++) {     // f quad, b0 at fp, b1 at fp+4
                float4 pa = sIn[w][q2][0][fp];
                float4 pb = sIn[w][q2][0][fp + 4];
                acc0 = fmaf(pa.x, wz[4*fp], acc0);   acc1 = fmaf(pb.x, wz[4*fp], acc1);
                acc0 = fmaf(pa.y, wz[4*fp+1], acc0); acc1 = fmaf(pb.y, wz[4*fp+1], acc1);
                acc0 = fmaf(pa.z, wz[4*fp+2], acc0); acc1 = fmaf(pb.z, wz[4*fp+2], acc1);
                acc0 = fmaf(pa.w, wz[4*fp+3], acc0); acc1 = fmaf(pb.w, wz[4*fp+3], acc1);
                float4 ta = sIn[w][q2][1][fp];
                float4 tb = sIn[w][q2][1][fp + 4];
                acc0 = fmaf(ta.x, ww[4*fp], acc0);   acc1 = fmaf(tb.x, ww[4*fp], acc1);
                acc0 = fmaf(ta.y, ww[4*fp+1], acc0); acc1 = fmaf(tb.y, ww[4*fp+1], acc1);
                acc0 = fmaf(ta.z, ww[4*fp+2], acc0); acc1 = fmaf(tb.z, ww[4*fp+2], acc1);
                acc0 = fmaf(ta.w, ww[4*fp+3], acc0); acc1 = fmaf(tb.w, ww[4*fp+3], acc1);
                float4 sa = sIn[w][q2][2][fp];
                float4 sb = sIn[w][q2][2][fp + 4];
                acc0 = fmaf(sa.x, wu[4*fp], acc0);   acc1 = fmaf(sb.x, wu[4*fp], acc1);
                acc0 = fmaf(sa.y, wu[4*fp+1], acc0); acc1 = fmaf(sb.y, wu[4*fp+1], acc1);
                acc0 = fmaf(sa.z, wu[4*fp+2], acc0); acc1 = fmaf(sb.z, wu[4*fp+2], acc1);
                acc0 = fmaf(sa.w, wu[4*fp+3], acc0); acc1 = fmaf(sb.w, wu[4*fp+3], acc1);
            }
            size_t row = (size_t)(v0 + q2) * 64;
            g_h1h[row + lane] = __float2half_rn(acc0);
            g_h1h[row + 32 + lane] = __float2half_rn(acc1);
            ls += acc0 + acc1;
            lss = fmaf(acc0, acc0, lss);
            lss = fmaf(acc1, acc1, lss);
        }
        __syncwarp();
    }
    atomicAdd(&bsum[lane], ls);
    atomicAdd(&bss[lane], lss);
    __syncthreads();
    if (tid < 32) {
        atomicAdd(&g_stats[tid], bsum[tid]);
        atomicAdd(&g_stats[32 + tid], bss[tid]);
    }
}

// ---------------- K3: t2 = L relu(bn1(h1)) (fp16 rows, local finalize) ------
__global__ void k_spmv64_bn(const int* __restrict__ cols,
                            const float* __restrict__ vals,
                            const float* __restrict__ gamma,
                            const float* __restrict__ beta) {
    __shared__ __align__(16) float s_sc[32], s_bi[32];
    int tid = threadIdx.x;
    if (tid < 32) {
        float n = (float)(2 * NV);
        float mean = g_stats[tid] / n;
        float var = g_stats[32 + tid] / n - mean * mean;
        float rstd = rsqrtf(var + 1e-5f);
        float sc = gamma[tid] * rstd;
        s_sc[tid] = sc;
        s_bi[tid] = beta[tid] - mean * sc;
    }
    __syncthreads();
    int lane = tid & 31;
    int q = lane >> 4, r = lane & 15;
    int gw = (blockIdx.x * blockDim.x + tid) >> 5;
    int nw = (gridDim.x * blockDim.x) >> 5;
    int step = nw * 2;
    int ch = (4 * r) & 31;
    float4 sc4 = *(const float4*)(s_sc + ch);
    float4 bi4 = *(const float4*)(s_bi + ch);
    int v0 = gw * 2;
    int cjN = 0, c8N = 0; float ajN = 0.0f, a8N = 0.0f;
    if (v0 < NV) {
        int eb = (v0 + q) * DEG;
        cjN = (r < 8) ? cols[eb + r] : 0;
        ajN = (r < 8) ? vals[eb + r] : 0.0f;
        c8N = cols[eb + 8]; a8N = vals[eb + 8];
    }
    for (; v0 < NV; v0 += step) {
        int v = v0 + q;
        int cj = cjN; float aj = ajN; int c8 = c8N; float a8 = a8N;
        int vn = v0 + step;
        if (vn < NV) {
            int eb = (vn + q) * DEG;
            cjN = (r < 8) ? cols[eb + r] : 0;
            ajN = (r < 8) ? vals[eb + r] : 0.0f;
            c8N = cols[eb + 8]; a8N = vals[eb + 8];
        }
        float4 acc = make_float4(0.f, 0.f, 0.f, 0.f);
        #pragma unroll
        for (int j = 0; j < 8; j++) {
            int   c = __shfl_sync(0xffffffffu, cj, (q << 4) + j);
            float a = __shfl_sync(0xffffffffu, aj, (q << 4) + j);
            H4 g; g.u = *(const ull*)(g_h1h + (size_t)c * 64 + 4 * r);
            float2 lo = __half22float2(g.h[0]);
            float2 hi = __half22float2(g.h[1]);
            acc.x = fmaf(a, fmaxf(fmaf(lo.x, sc4.x, bi4.x), 0.0f), acc.x);
            acc.y = fmaf(a, fmaxf(fmaf(lo.y, sc4.y, bi4.y), 0.0f), acc.y);
            acc.z = fmaf(a, fmaxf(fmaf(hi.x, sc4.z, bi4.z), 0.0f), acc.z);
            acc.w = fmaf(a, fmaxf(fmaf(hi.y, sc4.w, bi4.w), 0.0f), acc.w);
        }
        {
            H4 g; g.u = *(const ull*)(g_h1h + (size_t)c8 * 64 + 4 * r);
            float2 lo = __half22float2(g.h[0]);
            float2 hi = __half22float2(g.h[1]);
            acc.x = fmaf(a8, fmaxf(fmaf(lo.x, sc4.x, bi4.x), 0.0f), acc.x);
            acc.y = fmaf(a8, fmaxf(fmaf(lo.y, sc4.y, bi4.y), 0.0f), acc.y);
            acc.z = fmaf(a8, fmaxf(fmaf(hi.x, sc4.z, bi4.z), 0.0f), acc.z);
            acc.w = fmaf(a8, fmaxf(fmaf(hi.y, sc4.w, bi4.w), 0.0f), acc.w);
        }
        *(ull*)(g_t2h + (size_t)v * 64 + 4 * r) = pack_h4(acc.x, acc.y, acc.z, acc.w);
    }
}

// ---------------- K4: fused layer2 (fp16 gathers/streams, local finalize) ---
__global__ void __launch_bounds__(128) k_fused2(const int* __restrict__ cols,
                                                const float* __restrict__ vals,
                                                const float* __restrict__ W2,
                                                const float* __restrict__ gamma,
                                                const float* __restrict__ beta) {
    __shared__ float4 sIn[4][2][3][16];      // [warp][slot][arr][quad]
    __shared__ float bsum[32], bss[32];
    __shared__ __align__(16) float s_sc[32], s_bi[32];
    int tid = threadIdx.x, lane = tid & 31, w = tid >> 5;
    int q = lane >> 4, r = lane & 15;
    if (tid < 32) { bsum[tid] = 0.0f; bss[tid] = 0.0f; }
    if (tid >= 32 && tid < 64) {
        int c = tid - 32;
        float n = (float)(2 * NV);
        float mean = g_stats[c] / n;
        float var = g_stats[32 + c] / n - mean * mean;
        float rstd = rsqrtf(var + 1e-5f);
        float sc = gamma[c] * rstd;
        s_sc[c] = sc;
        s_bi[c] = beta[c] - mean * sc;
    }
    float wa[32], wt[32], ws[32];
    #pragma unroll
    for (int f = 0; f < 32; f++) {
        float a = W2[f * 32 + lane];
        float b = W2[1024 + f * 32 + lane];
        float c = W2[2048 + f * 32 + lane];
        wa[f] = a - c; wt[f] = b; ws[f] = 2.0f * c;
    }
    __syncthreads();
    int ch = (4 * r) & 31;
    float4 sc4 = *(const float4*)(s_sc + ch);
    float4 bi4 = *(const float4*)(s_bi + ch);

    int gw = blockIdx.x * 4 + w, nw = gridDim.x * 4;
    int step = nw * 2;
    float ls = 0.0f, lss = 0.0f;
    int v0 = gw * 2;
    int cjN = 0, c8N = 0; float ajN = 0.0f, a8N = 0.0f;
    if (v0 < NV) {
        int eb = (v0 + q) * DEG;
        cjN = (r < 8) ? cols[eb + r] : 0;
        ajN = (r < 8) ? vals[eb + r] : 0.0f;
        c8N = cols[eb + 8]; a8N = vals[eb + 8];
    }

    for (; v0 < NV; v0 += step) {
        int v = v0 + q;
        int cj = cjN; float aj = ajN; int c8 = c8N; float a8 = a8N;
        int vn = v0 + step;
        if (vn < NV) {
            int eb = (vn + q) * DEG;
            cjN = (r < 8) ? cols[eb + r] : 0;
            ajN = (r < 8) ? vals[eb + r] : 0.0f;
            c8N = cols[eb + 8]; a8N = vals[eb + 8];
        }
        float4 s4 = make_float4(0.f, 0.f, 0.f, 0.f);
        #pragma unroll
        for (int j = 0; j < 8; j++) {
            int   c = __shfl_sync(0xffffffffu, cj, (q << 4) + j);
            float a = __shfl_sync(0xffffffffu, aj, (q << 4) + j);
            H4 g; g.u = *(const ull*)(g_t2h + (size_t)c * 64 + 4 * r);
            float2 lo = __half22float2(g.h[0]);
            float2 hi = __half22float2(g.h[1]);
            s4.x = fmaf(a, lo.x, s4.x); s4.y = fmaf(a, lo.y, s4.y);
            s4.z = fmaf(a, hi.x, s4.z); s4.w = fmaf(a, hi.y, s4.w);
        }
        {
            H4 g; g.u = *(const ull*)(g_t2h + (size_t)c8 * 64 + 4 * r);
            float2 lo = __half22float2(g.h[0]);
            float2 hi = __half22float2(g.h[1]);
            s4.x = fmaf(a8, lo.x, s4.x); s4.y = fmaf(a8, lo.y, s4.y);
            s4.z = fmaf(a8, hi.x, s4.z); s4.w = fmaf(a8, hi.y, s4.w);
        }
        float4 a14, t4;
        {
            H4 g; g.u = *(const ull*)(g_h1h + (size_t)v * 64 + 4 * r);
            float2 lo = __half22float2(g.h[0]);
            float2 hi = __half22float2(g.h[1]);
            a14.x = fmaxf(fmaf(lo.x, sc4.x, bi4.x), 0.0f);
            a14.y = fmaxf(fmaf(lo.y, sc4.y, bi4.y), 0.0f);
            a14.z = fmaxf(fmaf(hi.x, sc4.z, bi4.z), 0.0f);
            a14.w = fmaxf(fmaf(hi.y, sc4.w, bi4.w), 0.0f);
        }
        {
            H4 g; g.u = *(const ull*)(g_t2h + (size_t)v * 64 + 4 * r);
            float2 lo = __half22float2(g.h[0]);
            float2 hi = __half22float2(g.h[1]);
            t4.x = lo.x; t4.y = lo.y; t4.z = hi.x; t4.w = hi.y;
        }
        sIn[w][q][0][r] = a14;
        sIn[w][q][1][r] = t4;
        sIn[w][q][2][r] = s4;
        __syncwarp();
        #pragma unroll
        for (int q2 = 0; q2 < 2; q2++) {
            float acc0 = 0.0f, acc1 = 0.0f;
            #pragma unroll
            for (int fp = 0; fp < 8; fp++) {     // f quad, b0 at fp, b1 at fp+8
                float4 pa = sIn[w][q2][0][fp];
                float4 pb = sIn[w][q2][0][fp + 8];
                acc0 = fmaf(pa.x, wa[4*fp], acc0);   acc1 = fmaf(pb.x, wa[4*fp], acc1);
                acc0 = fmaf(pa.y, wa[4*fp+1], acc0); acc1 = fmaf(pb.y, wa[4*fp+1], acc1);
                acc0 = fmaf(pa.z, wa[4*fp+2], acc0); acc1 = fmaf(pb.z, wa[4*fp+2], acc1);
                acc0 = fmaf(pa.w, wa[4*fp+3], acc0); acc1 = fmaf(pb.w, wa[4*fp+3], acc1);
                float4 ta = sIn[w][q2][1][fp];
                float4 tb = sIn[w][q2][1][fp + 8];
                acc0 = fmaf(ta.x, wt[4*fp], acc0);   acc1 = fmaf(tb.x, wt[4*fp], acc1);
                acc0 = fmaf(ta.y, wt[4*fp+1], acc0); acc1 = fmaf(tb.y, wt[4*fp+1], acc1);
                acc0 = fmaf(ta.z, wt[4*fp+2], acc0); acc1 = fmaf(tb.z, wt[4*fp+2], acc1);
                acc0 = fmaf(ta.w, wt[4*fp+3], acc0); acc1 = fmaf(tb.w, wt[4*fp+3], acc1);
                float4 sa = sIn[w][q2][2][fp];
                float4 sb = sIn[w][q2][2][fp + 8];
                acc0 = fmaf(sa.x, ws[4*fp], acc0);   acc1 = fmaf(sb.x, ws[4*fp], acc1);
                acc0 = fmaf(sa.y, ws[4*fp+1], acc0); acc1 = fmaf(sb.y, ws[4*fp+1], acc1);
                acc0 = fmaf(sa.z, ws[4*fp+2], acc0); acc1 = fmaf(sb.z, ws[4*fp+2], acc1);
                acc0 = fmaf(sa.w, ws[4*fp+3], acc0); acc1 = fmaf(sb.w, ws[4*fp+3], acc1);
            }
            g_h2[(size_t)(v0 + q2) * 64 + lane] = acc0;
            g_h2[(size_t)(v0 + q2) * 64 + 32 + lane] = acc1;
            ls += acc0 + acc1;
            lss = fmaf(acc0, acc0, lss);
            lss = fmaf(acc1, acc1, lss);
        }
        __syncwarp();
    }
    atomicAdd(&bsum[lane], ls);
    atomicAdd(&bss[lane], lss);
    __syncthreads();
    if (tid < 32) {
        atomicAdd(&g_stats[64 + tid], bsum[tid]);
        atomicAdd(&g_stats[96 + tid], bss[tid]);
    }
}

// ---------------- K5: out = relu(bn2(h2)), local finalize -------------------
__global__ void k_output(float* __restrict__ out,
                         const float* __restrict__ gamma,
                         const float* __restrict__ beta) {
    __shared__ float s_sc[32], s_bi[32];
    int tid = threadIdx.x;
    if (tid < 32) {
        float n = (float)(2 * NV);
        float mean = g_stats[64 + tid] / n;
        float var = g_stats[96 + tid] / n - mean * mean;
        float rstd = rsqrtf(var + 1e-5f);
        float sc = gamma[tid] * rstd;
        s_sc[tid] = sc;
        s_bi[tid] = beta[tid] - mean * sc;
    }
    __syncthreads();
    const int total = NV * 16;
    for (int idx = blockIdx.x * blockDim.x + tid; idx < total;
         idx += gridDim.x * blockDim.x) {
        int v = idx >> 4;
        int j = idx & 15;
        int col = j * 4;
        int ch = col & 31;
        int b = col >> 5;
        float4 hv = *(const float4*)(g_h2 + (size_t)v * 64 + col);
        float4 r;
        r.x = fmaxf(fmaf(hv.x, s_sc[ch],     s_bi[ch]),     0.0f);
        r.y = fmaxf(fmaf(hv.y, s_sc[ch + 1], s_bi[ch + 1]), 0.0f);
        r.z = fmaxf(fmaf(hv.z, s_sc[ch + 2], s_bi[ch + 2]), 0.0f);
        r.w = fmaxf(fmaf(hv.w, s_sc[ch + 3], s_bi[ch + 3]), 0.0f);
        *(float4*)(out + (size_t)b * NV * 32 + (size_t)v * 32 + ch) = r;
    }
}

// ---------------- launch ----------------------------------------------------
extern "C" void kernel_launch(void* const* d_in, const int* in_sizes, int n_in,
                              void* d_out, int out_size) {
    const float* x    = (const float*)d_in[0];
    const int*   cols = (const int*)d_in[2];
    const float* vals = (const float*)d_in[3];
    const float* W1   = (const float*)d_in[4];
    const float* g1   = (const float*)d_in[5];
    const float* b1   = (const float*)d_in[6];
    const float* W2   = (const float*)d_in[7];
    const float* g2   = (const float*)d_in[8];
    const float* b2   = (const float*)d_in[9];
    float*       out  = (float*)d_out;

    const int GRID_G = 1184;      // gather kernels, 256 thr
    const int GRID_F = 2368;      // fused kernels, 128 thr

    k_spmv32<<<GRID_G, 256>>>(cols, vals, x);
    k_fused1<<<GRID_F, 128>>>(cols, vals, W1, x);
    k_spmv64_bn<<<GRID_G, 256>>>(cols, vals, g1, b1);
    k_fused2<<<GRID_F, 128>>>(cols, vals, W2, g1, b1);
    k_output<<<2048, 256>>>(out, g2, b2);
}